// round 1
// baseline (speedup 1.0000x reference)
#include <cuda_runtime.h>
#include <math.h>

#define T_SIZE 524288u
#define T_MASK (T_SIZE - 1u)
#define HPI2 2654435761u
#define HPI3 805459861u

__constant__ float c_NL[16] = {16.f, 22.f, 30.f, 42.f, 58.f, 80.f, 111.f, 153.f,
                               212.f, 293.f, 406.f, 561.f, 775.f, 1071.f, 1481.f, 2046.f};

__global__ __launch_bounds__(128)
void ngp_fwd(const float* __restrict__ x, const float* __restrict__ dvec,
             const float* __restrict__ tables,
             const float* __restrict__ dW1, const float* __restrict__ db1,
             const float* __restrict__ dW2, const float* __restrict__ db2,
             const float* __restrict__ cW1, const float* __restrict__ cb1,
             const float* __restrict__ cW2, const float* __restrict__ cb2,
             const float* __restrict__ cW3, const float* __restrict__ cb3,
             float* __restrict__ out, int n)
{
    // ---- stage all weights in shared memory (uniform broadcast reads later) ----
    __shared__ float s_dW1[32 * 64];   // 2048
    __shared__ float s_db1[64];
    __shared__ float s_dW2[64 * 16];   // 1024
    __shared__ float s_db2[16];
    __shared__ float s_cW1[43 * 64];   // 2752
    __shared__ float s_cb1[64];
    __shared__ float s_cW2[64 * 64];   // 4096
    __shared__ float s_cb2[64];
    __shared__ float s_cW3[64 * 3];    // 192
    __shared__ float s_cb3[3];

    const int t = threadIdx.x;
    for (int i = t; i < 2048; i += 128) s_dW1[i] = dW1[i];
    for (int i = t; i < 64;   i += 128) s_db1[i] = db1[i];
    for (int i = t; i < 1024; i += 128) s_dW2[i] = dW2[i];
    for (int i = t; i < 16;   i += 128) s_db2[i] = db2[i];
    for (int i = t; i < 2752; i += 128) s_cW1[i] = cW1[i];
    for (int i = t; i < 64;   i += 128) s_cb1[i] = cb1[i];
    for (int i = t; i < 4096; i += 128) s_cW2[i] = cW2[i];
    for (int i = t; i < 64;   i += 128) s_cb2[i] = cb2[i];
    for (int i = t; i < 192;  i += 128) s_cW3[i] = cW3[i];
    for (int i = t; i < 3;    i += 128) s_cb3[i] = cb3[i];
    __syncthreads();

    const int idx = blockIdx.x * blockDim.x + threadIdx.x;
    if (idx >= n) return;

    // ---- load point, compute mask and normalized coords ----
    const float x0 = x[3 * idx + 0];
    const float x1 = x[3 * idx + 1];
    const float x2 = x[3 * idx + 2];
    const float xs0 = x0 / 3.0f;
    const float xs1 = x1 / 3.0f;
    const float xs2 = x2 / 3.0f;
    const bool mask = (fabsf(xs0) < 0.5f) && (fabsf(xs1) < 0.5f) && (fabsf(xs2) < 0.5f);
    const float xc0 = fminf(fmaxf(xs0 + 0.5f, 0.0f), 1.0f);
    const float xc1 = fminf(fmaxf(xs1 + 0.5f, 0.0f), 1.0f);
    const float xc2 = fminf(fmaxf(xs2 + 0.5f, 0.0f), 1.0f);

    // ---- density MLP layer 1, accumulated level-by-level (keeps feats out of regs) ----
    float h1[64];
    #pragma unroll
    for (int j = 0; j < 64; j++) h1[j] = s_db1[j];

    const float2* __restrict__ tb2 = (const float2*)tables;

    #pragma unroll 1
    for (int lev = 0; lev < 16; lev++) {
        const float nl = c_NL[lev];
        const float xn0 = xc0 * nl;
        const float xn1 = xc1 * nl;
        const float xn2 = xc2 * nl;
        const float fl0 = floorf(xn0), fl1 = floorf(xn1), fl2 = floorf(xn2);
        const float w0 = xn0 - fl0, w1 = xn1 - fl1, w2 = xn2 - fl2;
        const float v0 = 1.0f - w0, v1 = 1.0f - w1, v2 = 1.0f - w2;

        const unsigned int f0 = (unsigned int)fl0;
        const unsigned int f1 = (unsigned int)fl1;
        const unsigned int f2 = (unsigned int)fl2;
        const unsigned int cx = (unsigned int)ceilf(xn0);
        const unsigned int cy = (unsigned int)ceilf(xn1);
        const unsigned int cz = (unsigned int)ceilf(xn2);

        // pre-multiplied hash components
        const unsigned int hxf = f0;           const unsigned int hxc = cx;
        const unsigned int hyf = f1 * HPI2;    const unsigned int hyc = cy * HPI2;
        const unsigned int hzf = f2 * HPI3;    const unsigned int hzc = cz * HPI3;

        const float2* __restrict__ tl = tb2 + (size_t)lev * T_SIZE;

        float fa = 0.0f, fb = 0.0f;
        #pragma unroll
        for (int v = 0; v < 8; v++) {
            const unsigned int h = (((v & 1) ? hxc : hxf)
                                  ^ ((v & 2) ? hyc : hyf)
                                  ^ ((v & 4) ? hzc : hzf)) & T_MASK;
            const float2 e = __ldg(tl + h);
            const float wc = ((v & 1) ? w0 : v0) * ((v & 2) ? w1 : v1) * ((v & 4) ? w2 : v2);
            fa = fmaf(wc, e.x, fa);
            fb = fmaf(wc, e.y, fb);
        }

        // accumulate into density hidden layer: rows 2*lev and 2*lev+1 of dW1
        const float4* __restrict__ Wa = (const float4*)(s_dW1 + (2 * lev) * 64);
        const float4* __restrict__ Wb = (const float4*)(s_dW1 + (2 * lev + 1) * 64);
        #pragma unroll
        for (int j = 0; j < 16; j++) {
            const float4 a = Wa[j];
            const float4 b = Wb[j];
            h1[4 * j + 0] = fmaf(fa, a.x, fmaf(fb, b.x, h1[4 * j + 0]));
            h1[4 * j + 1] = fmaf(fa, a.y, fmaf(fb, b.y, h1[4 * j + 1]));
            h1[4 * j + 2] = fmaf(fa, a.z, fmaf(fb, b.z, h1[4 * j + 2]));
            h1[4 * j + 3] = fmaf(fa, a.w, fmaf(fb, b.w, h1[4 * j + 3]));
        }
    }

    // relu
    #pragma unroll
    for (int j = 0; j < 64; j++) h1[j] = fmaxf(h1[j], 0.0f);

    // ---- density MLP layer 2: 64 -> 16 (no relu) ----
    float4 hA = *(const float4*)(s_db2 + 0);
    float4 hB = *(const float4*)(s_db2 + 4);
    float4 hC = *(const float4*)(s_db2 + 8);
    float4 hD = *(const float4*)(s_db2 + 12);
    #pragma unroll
    for (int i = 0; i < 64; i++) {
        const float hv = h1[i];
        const float4* __restrict__ r = (const float4*)(s_dW2 + i * 16);
        const float4 r0 = r[0], r1 = r[1], r2 = r[2], r3 = r[3];
        hA.x = fmaf(hv, r0.x, hA.x); hA.y = fmaf(hv, r0.y, hA.y); hA.z = fmaf(hv, r0.z, hA.z); hA.w = fmaf(hv, r0.w, hA.w);
        hB.x = fmaf(hv, r1.x, hB.x); hB.y = fmaf(hv, r1.y, hB.y); hB.z = fmaf(hv, r1.z, hB.z); hB.w = fmaf(hv, r1.w, hB.w);
        hC.x = fmaf(hv, r2.x, hC.x); hC.y = fmaf(hv, r2.y, hC.y); hC.z = fmaf(hv, r2.z, hC.z); hC.w = fmaf(hv, r2.w, hC.w);
        hD.x = fmaf(hv, r3.x, hD.x); hD.y = fmaf(hv, r3.y, hD.y); hD.z = fmaf(hv, r3.z, hD.z); hD.w = fmaf(hv, r3.w, hD.w);
    }
    float h16[16];
    h16[0] = hA.x; h16[1] = hA.y; h16[2]  = hA.z; h16[3]  = hA.w;
    h16[4] = hB.x; h16[5] = hB.y; h16[6]  = hB.z; h16[7]  = hB.w;
    h16[8] = hC.x; h16[9] = hC.y; h16[10] = hC.z; h16[11] = hC.w;
    h16[12] = hD.x; h16[13] = hD.y; h16[14] = hD.z; h16[15] = hD.w;

    // ---- build color MLP input: [h16 (16), d (3), sin/cos freqs (24)] = 43 ----
    float cin[43];
    #pragma unroll
    for (int i = 0; i < 16; i++) cin[i] = h16[i];
    const float d0 = dvec[3 * idx + 0];
    const float d1 = dvec[3 * idx + 1];
    const float d2 = dvec[3 * idx + 2];
    cin[16] = d0; cin[17] = d1; cin[18] = d2;
    {
        float f = 1.0f;
        int p = 19;
        #pragma unroll
        for (int i = 0; i < 4; i++) {
            float s0, c0, s1, c1, s2, c2;
            sincosf(f * d0, &s0, &c0);
            sincosf(f * d1, &s1, &c1);
            sincosf(f * d2, &s2, &c2);
            cin[p + 0] = s0; cin[p + 1] = s1; cin[p + 2] = s2;
            cin[p + 3] = c0; cin[p + 4] = c1; cin[p + 5] = c2;
            p += 6;
            f *= 2.0f;
        }
    }

    // ---- color MLP layer 1: 43 -> 64, relu ----
    float g1[64];
    #pragma unroll
    for (int j = 0; j < 64; j++) g1[j] = s_cb1[j];
    #pragma unroll
    for (int i = 0; i < 43; i++) {
        const float v = cin[i];
        const float4* __restrict__ r = (const float4*)(s_cW1 + i * 64);
        #pragma unroll
        for (int j = 0; j < 16; j++) {
            const float4 w = r[j];
            g1[4 * j + 0] = fmaf(v, w.x, g1[4 * j + 0]);
            g1[4 * j + 1] = fmaf(v, w.y, g1[4 * j + 1]);
            g1[4 * j + 2] = fmaf(v, w.z, g1[4 * j + 2]);
            g1[4 * j + 3] = fmaf(v, w.w, g1[4 * j + 3]);
        }
    }
    #pragma unroll
    for (int j = 0; j < 64; j++) g1[j] = fmaxf(g1[j], 0.0f);

    // ---- color MLP layer 2: 64 -> 64, relu ----
    float g2[64];
    #pragma unroll
    for (int j = 0; j < 64; j++) g2[j] = s_cb2[j];
    #pragma unroll
    for (int i = 0; i < 64; i++) {
        const float v = g1[i];
        const float4* __restrict__ r = (const float4*)(s_cW2 + i * 64);
        #pragma unroll
        for (int j = 0; j < 16; j++) {
            const float4 w = r[j];
            g2[4 * j + 0] = fmaf(v, w.x, g2[4 * j + 0]);
            g2[4 * j + 1] = fmaf(v, w.y, g2[4 * j + 1]);
            g2[4 * j + 2] = fmaf(v, w.z, g2[4 * j + 2]);
            g2[4 * j + 3] = fmaf(v, w.w, g2[4 * j + 3]);
        }
    }

    // ---- color MLP layer 3: 64 -> 3, sigmoid ----
    float o0 = s_cb3[0], o1 = s_cb3[1], o2 = s_cb3[2];
    #pragma unroll
    for (int i = 0; i < 64; i++) {
        const float v = fmaxf(g2[i], 0.0f);
        o0 = fmaf(v, s_cW3[i * 3 + 0], o0);
        o1 = fmaf(v, s_cW3[i * 3 + 1], o1);
        o2 = fmaf(v, s_cW3[i * 3 + 2], o2);
    }
    const float col0 = 1.0f / (1.0f + expf(-o0));
    const float col1 = 1.0f / (1.0f + expf(-o1));
    const float col2 = 1.0f / (1.0f + expf(-o2));

    // ---- write outputs: color [n,3] then sigma [n] ----
    if (mask) {
        out[3 * idx + 0] = col0;
        out[3 * idx + 1] = col1;
        out[3 * idx + 2] = col2;
        out[3 * n + idx] = expf(h16[0]);
    } else {
        out[3 * idx + 0] = 0.0f;
        out[3 * idx + 1] = 0.0f;
        out[3 * idx + 2] = 0.0f;
        out[3 * n + idx] = 0.0f;   // exp(-10000) underflows to 0
    }
}

extern "C" void kernel_launch(void* const* d_in, const int* in_sizes, int n_in,
                              void* d_out, int out_size) {
    const float* x      = (const float*)d_in[0];
    const float* d      = (const float*)d_in[1];
    const float* tables = (const float*)d_in[2];
    const float* dW1    = (const float*)d_in[3];
    const float* db1    = (const float*)d_in[4];
    const float* dW2    = (const float*)d_in[5];
    const float* db2    = (const float*)d_in[6];
    const float* cW1    = (const float*)d_in[7];
    const float* cb1    = (const float*)d_in[8];
    const float* cW2    = (const float*)d_in[9];
    const float* cb2    = (const float*)d_in[10];
    const float* cW3    = (const float*)d_in[11];
    const float* cb3    = (const float*)d_in[12];
    float* out = (float*)d_out;

    const int n = in_sizes[0] / 3;
    const int threads = 128;
    const int blocks = (n + threads - 1) / threads;
    ngp_fwd<<<blocks, threads>>>(x, d, tables, dW1, db1, dW2, db2,
                                 cW1, cb1, cW2, cb2, cW3, cb3, out, n);
}

// round 2
// speedup vs baseline: 1.5649x; 1.5649x over previous
#include <cuda_runtime.h>
#include <math.h>

typedef unsigned int u32;
typedef unsigned long long u64;

#define T_SIZE 524288u
#define T_MASK (T_SIZE - 1u)
#define HPI2 2654435761u
#define HPI3 805459861u
#define MAXN 1048576

__device__ int g_cnt;
__device__ int g_idx[MAXN];

__constant__ float c_NL[16] = {16.f, 22.f, 30.f, 42.f, 58.f, 80.f, 111.f, 153.f,
                               212.f, 293.f, 406.f, 561.f, 775.f, 1071.f, 1481.f, 2046.f};

// ---- f32x2 packed-FMA helpers (sm_103a FFMA2 — only reachable via PTX) ----
__device__ __forceinline__ u64 fma2(u64 a, u64 b, u64 c) {
    u64 d;
    asm("fma.rn.f32x2 %0, %1, %2, %3;" : "=l"(d) : "l"(a), "l"(b), "l"(c));
    return d;
}
__device__ __forceinline__ u64 dup2(float v) {
    u64 d;
    asm("mov.b64 %0, {%1, %1};" : "=l"(d) : "f"(v));
    return d;
}
__device__ __forceinline__ float2 unpack2(u64 v) {
    float2 r;
    asm("mov.b64 {%0, %1}, %2;" : "=f"(r.x), "=f"(r.y) : "l"(v));
    return r;
}

// ------------------------------------------------------------------
// Kernel 0: reset compaction counter
// ------------------------------------------------------------------
__global__ void reset_kernel() { g_cnt = 0; }

// ------------------------------------------------------------------
// Kernel 1: compute mask, zero outputs of masked points, compact live indices
// ------------------------------------------------------------------
__global__ __launch_bounds__(256)
void mask_zero_compact(const float* __restrict__ x, float* __restrict__ out, int n) {
    const int i = blockIdx.x * blockDim.x + threadIdx.x;
    const bool valid = (i < n);
    bool m = false;
    if (valid) {
        const float xs0 = x[3 * i + 0] / 3.0f;
        const float xs1 = x[3 * i + 1] / 3.0f;
        const float xs2 = x[3 * i + 2] / 3.0f;
        m = (fabsf(xs0) < 0.5f) && (fabsf(xs1) < 0.5f) && (fabsf(xs2) < 0.5f);
    }
    const u32 bal = __ballot_sync(0xffffffffu, m);
    const int lane = threadIdx.x & 31;
    int base = 0;
    if (lane == 0 && bal) base = atomicAdd(&g_cnt, __popc(bal));
    base = __shfl_sync(0xffffffffu, base, 0);
    if (m) {
        g_idx[base + __popc(bal & ((1u << lane) - 1u))] = i;
    } else if (valid) {
        out[3 * i + 0] = 0.0f;
        out[3 * i + 1] = 0.0f;
        out[3 * i + 2] = 0.0f;
        out[3 * n + i] = 0.0f;   // exp(-10000) underflows to 0
    }
}

// ------------------------------------------------------------------
// hash fetch for one level: issue 8 gathers + trilinear weights
// ------------------------------------------------------------------
__device__ __forceinline__ void hash_fetch(int lev, float xc0, float xc1, float xc2,
                                           const float2* __restrict__ tb2,
                                           float2 e[8], float& w0, float& w1, float& w2) {
    const float nl = c_NL[lev];
    const float xn0 = xc0 * nl, xn1 = xc1 * nl, xn2 = xc2 * nl;
    const float fl0 = floorf(xn0), fl1 = floorf(xn1), fl2 = floorf(xn2);
    w0 = xn0 - fl0; w1 = xn1 - fl1; w2 = xn2 - fl2;
    const u32 f0 = (u32)fl0, f1 = (u32)fl1, f2 = (u32)fl2;
    const u32 cx = (u32)ceilf(xn0), cy = (u32)ceilf(xn1), cz = (u32)ceilf(xn2);
    const u32 hyf = f1 * HPI2, hyc = cy * HPI2;
    const u32 hzf = f2 * HPI3, hzc = cz * HPI3;
    const float2* __restrict__ tl = tb2 + (size_t)lev * T_SIZE;
    #pragma unroll
    for (int v = 0; v < 8; v++) {
        const u32 h = (((v & 1) ? cx : f0)
                     ^ ((v & 2) ? hyc : hyf)
                     ^ ((v & 4) ? hzc : hzf)) & T_MASK;
        e[v] = __ldg(tl + h);
    }
}

// accumulate one level's interpolated features into packed h1 (rows 2*lev, 2*lev+1 of dW1)
__device__ __forceinline__ void accum_level(int lev, const float2 e[8],
                                            float w0, float w1, float w2,
                                            const float* __restrict__ s_dW1, u64 h1x2[32]) {
    const float v0 = 1.0f - w0, v1 = 1.0f - w1, v2 = 1.0f - w2;
    float fa = 0.0f, fb = 0.0f;
    #pragma unroll
    for (int v = 0; v < 8; v++) {
        const float wc = ((v & 1) ? w0 : v0) * ((v & 2) ? w1 : v1) * ((v & 4) ? w2 : v2);
        fa = fmaf(wc, e[v].x, fa);
        fb = fmaf(wc, e[v].y, fb);
    }
    const u64 dA = dup2(fa), dB = dup2(fb);
    const ulonglong2* __restrict__ Wa = (const ulonglong2*)(s_dW1 + lev * 128);
    const ulonglong2* __restrict__ Wb = Wa + 16;   // next row = +64 floats = +16 ulonglong2
    #pragma unroll
    for (int k = 0; k < 16; k++) {
        const ulonglong2 a = Wa[k];
        const ulonglong2 b = Wb[k];
        h1x2[2 * k + 0] = fma2(dA, a.x, fma2(dB, b.x, h1x2[2 * k + 0]));
        h1x2[2 * k + 1] = fma2(dA, a.y, fma2(dB, b.y, h1x2[2 * k + 1]));
    }
}

// ------------------------------------------------------------------
// Kernel 2: main fused NGP forward on compacted live points
// ------------------------------------------------------------------
__global__ __launch_bounds__(128)
void ngp_fwd(const float* __restrict__ x, const float* __restrict__ dvec,
             const float* __restrict__ tables,
             const float* __restrict__ dW1, const float* __restrict__ db1,
             const float* __restrict__ dW2, const float* __restrict__ db2,
             const float* __restrict__ cW1, const float* __restrict__ cb1,
             const float* __restrict__ cW2, const float* __restrict__ cb2,
             const float* __restrict__ cW3, const float* __restrict__ cb3,
             float* __restrict__ out, int n)
{
    const int cnt = g_cnt;
    if (blockIdx.x * 128 >= cnt) return;   // block-uniform early exit (before any sync)

    __shared__ __align__(16) float s_dW1[32 * 64];
    __shared__ __align__(16) float s_db1[64];
    __shared__ __align__(16) float s_dW2[64 * 16];
    __shared__ __align__(16) float s_db2[16];
    __shared__ __align__(16) float s_cW1[43 * 64];
    __shared__ __align__(16) float s_cb1[64];
    __shared__ __align__(16) float s_cW2[64 * 64];
    __shared__ __align__(16) float s_cb2[64];
    __shared__ __align__(16) float s_cW3[64 * 3];
    __shared__ float s_cb3[3];

    const int t = threadIdx.x;
    for (int i = t; i < 2048; i += 128) s_dW1[i] = dW1[i];
    for (int i = t; i < 64;   i += 128) s_db1[i] = db1[i];
    for (int i = t; i < 1024; i += 128) s_dW2[i] = dW2[i];
    for (int i = t; i < 16;   i += 128) s_db2[i] = db2[i];
    for (int i = t; i < 2752; i += 128) s_cW1[i] = cW1[i];
    for (int i = t; i < 64;   i += 128) s_cb1[i] = cb1[i];
    for (int i = t; i < 4096; i += 128) s_cW2[i] = cW2[i];
    for (int i = t; i < 64;   i += 128) s_cb2[i] = cb2[i];
    for (int i = t; i < 192;  i += 128) s_cW3[i] = cW3[i];
    for (int i = t; i < 3;    i += 128) s_cb3[i] = cb3[i];
    __syncthreads();

    const int slot = blockIdx.x * 128 + threadIdx.x;
    if (slot >= cnt) return;
    const int idx = g_idx[slot];

    const float xc0 = fminf(fmaxf(x[3 * idx + 0] / 3.0f + 0.5f, 0.0f), 1.0f);
    const float xc1 = fminf(fmaxf(x[3 * idx + 1] / 3.0f + 0.5f, 0.0f), 1.0f);
    const float xc2 = fminf(fmaxf(x[3 * idx + 2] / 3.0f + 0.5f, 0.0f), 1.0f);

    const float2* __restrict__ tb2 = (const float2*)tables;

    // ---- density layer 1: packed accumulators, software-pipelined gathers ----
    u64 h1x2[32];
    {
        const ulonglong2* __restrict__ b = (const ulonglong2*)s_db1;
        #pragma unroll
        for (int k = 0; k < 16; k++) {
            const ulonglong2 v = b[k];
            h1x2[2 * k + 0] = v.x;
            h1x2[2 * k + 1] = v.y;
        }
    }

    float2 pe[8];
    float pw0, pw1, pw2;
    hash_fetch(0, xc0, xc1, xc2, tb2, pe, pw0, pw1, pw2);

    #pragma unroll 1
    for (int lev = 1; lev < 16; lev++) {
        float2 ne[8];
        float nw0, nw1, nw2;
        hash_fetch(lev, xc0, xc1, xc2, tb2, ne, nw0, nw1, nw2);   // loads in flight...
        accum_level(lev - 1, pe, pw0, pw1, pw2, s_dW1, h1x2);     // ...while we compute
        #pragma unroll
        for (int v = 0; v < 8; v++) pe[v] = ne[v];
        pw0 = nw0; pw1 = nw1; pw2 = nw2;
    }
    accum_level(15, pe, pw0, pw1, pw2, s_dW1, h1x2);

    // ---- density layer 2: 64 -> 16 (relu on inputs, packed accum) ----
    u64 h16x2[8];
    {
        const ulonglong2* __restrict__ b = (const ulonglong2*)s_db2;
        #pragma unroll
        for (int j = 0; j < 4; j++) {
            const ulonglong2 v = b[j];
            h16x2[2 * j + 0] = v.x;
            h16x2[2 * j + 1] = v.y;
        }
    }
    #pragma unroll
    for (int k = 0; k < 32; k++) {
        const float2 p = unpack2(h1x2[k]);
        const float a0 = fmaxf(p.x, 0.0f);
        const float a1 = fmaxf(p.y, 0.0f);
        const u64 d0 = dup2(a0), d1 = dup2(a1);
        const ulonglong2* __restrict__ r0 = (const ulonglong2*)(s_dW2 + (2 * k) * 16);
        const ulonglong2* __restrict__ r1 = r0 + 4;   // +16 floats
        #pragma unroll
        for (int j = 0; j < 4; j++) {
            const ulonglong2 A = r0[j];
            const ulonglong2 B = r1[j];
            h16x2[2 * j + 0] = fma2(d0, A.x, fma2(d1, B.x, h16x2[2 * j + 0]));
            h16x2[2 * j + 1] = fma2(d0, A.y, fma2(d1, B.y, h16x2[2 * j + 1]));
        }
    }

    // ---- build color MLP input cin[43] = [h16, d, sin/cos enc] ----
    float cin[43];
    #pragma unroll
    for (int j = 0; j < 8; j++) {
        const float2 p = unpack2(h16x2[j]);
        cin[2 * j + 0] = p.x;
        cin[2 * j + 1] = p.y;
    }
    const float sigma = expf(cin[0]);   // h[0] pre-anything else

    const float d0v = dvec[3 * idx + 0];
    const float d1v = dvec[3 * idx + 1];
    const float d2v = dvec[3 * idx + 2];
    cin[16] = d0v; cin[17] = d1v; cin[18] = d2v;
    {
        float f = 1.0f;
        int p = 19;
        #pragma unroll
        for (int i = 0; i < 4; i++) {
            float s0, c0, s1, c1, s2, c2;
            sincosf(f * d0v, &s0, &c0);
            sincosf(f * d1v, &s1, &c1);
            sincosf(f * d2v, &s2, &c2);
            cin[p + 0] = s0; cin[p + 1] = s1; cin[p + 2] = s2;
            cin[p + 3] = c0; cin[p + 4] = c1; cin[p + 5] = c2;
            p += 6;
            f *= 2.0f;
        }
    }

    // ---- color layer 1: 43 -> 64 (packed) ----
    u64 g1x2[32];
    {
        const ulonglong2* __restrict__ b = (const ulonglong2*)s_cb1;
        #pragma unroll
        for (int k = 0; k < 16; k++) {
            const ulonglong2 v = b[k];
            g1x2[2 * k + 0] = v.x;
            g1x2[2 * k + 1] = v.y;
        }
    }
    #pragma unroll
    for (int i = 0; i < 43; i++) {
        const u64 dv = dup2(cin[i]);
        const ulonglong2* __restrict__ r = (const ulonglong2*)(s_cW1 + i * 64);
        #pragma unroll
        for (int k = 0; k < 16; k++) {
            const ulonglong2 w = r[k];
            g1x2[2 * k + 0] = fma2(dv, w.x, g1x2[2 * k + 0]);
            g1x2[2 * k + 1] = fma2(dv, w.y, g1x2[2 * k + 1]);
        }
    }

    // ---- color layer 2: 64 -> 64 (relu inputs streamed from g1x2, packed) ----
    u64 g2x2[32];
    {
        const ulonglong2* __restrict__ b = (const ulonglong2*)s_cb2;
        #pragma unroll
        for (int k = 0; k < 16; k++) {
            const ulonglong2 v = b[k];
            g2x2[2 * k + 0] = v.x;
            g2x2[2 * k + 1] = v.y;
        }
    }
    #pragma unroll
    for (int k = 0; k < 32; k++) {
        const float2 p = unpack2(g1x2[k]);
        const float a0 = fmaxf(p.x, 0.0f);
        const float a1 = fmaxf(p.y, 0.0f);
        const u64 d0 = dup2(a0), d1 = dup2(a1);
        const ulonglong2* __restrict__ r0 = (const ulonglong2*)(s_cW2 + (2 * k) * 64);
        const ulonglong2* __restrict__ r1 = r0 + 16;   // +64 floats
        #pragma unroll
        for (int j = 0; j < 16; j++) {
            const ulonglong2 A = r0[j];
            const ulonglong2 B = r1[j];
            g2x2[2 * j + 0] = fma2(d0, A.x, fma2(d1, B.x, g2x2[2 * j + 0]));
            g2x2[2 * j + 1] = fma2(d0, A.y, fma2(d1, B.y, g2x2[2 * j + 1]));
        }
    }

    // ---- color layer 3: 64 -> 3, sigmoid ----
    float o0 = s_cb3[0], o1 = s_cb3[1], o2 = s_cb3[2];
    #pragma unroll
    for (int k = 0; k < 32; k++) {
        const float2 p = unpack2(g2x2[k]);
        const float a0 = fmaxf(p.x, 0.0f);
        const float a1 = fmaxf(p.y, 0.0f);
        const int i0 = 2 * k, i1 = 2 * k + 1;
        o0 = fmaf(a0, s_cW3[i0 * 3 + 0], o0);
        o1 = fmaf(a0, s_cW3[i0 * 3 + 1], o1);
        o2 = fmaf(a0, s_cW3[i0 * 3 + 2], o2);
        o0 = fmaf(a1, s_cW3[i1 * 3 + 0], o0);
        o1 = fmaf(a1, s_cW3[i1 * 3 + 1], o1);
        o2 = fmaf(a1, s_cW3[i1 * 3 + 2], o2);
    }

    out[3 * idx + 0] = 1.0f / (1.0f + expf(-o0));
    out[3 * idx + 1] = 1.0f / (1.0f + expf(-o1));
    out[3 * idx + 2] = 1.0f / (1.0f + expf(-o2));
    out[3 * n + idx] = sigma;
}

extern "C" void kernel_launch(void* const* d_in, const int* in_sizes, int n_in,
                              void* d_out, int out_size) {
    const float* x      = (const float*)d_in[0];
    const float* d      = (const float*)d_in[1];
    const float* tables = (const float*)d_in[2];
    const float* dW1    = (const float*)d_in[3];
    const float* db1    = (const float*)d_in[4];
    const float* dW2    = (const float*)d_in[5];
    const float* db2    = (const float*)d_in[6];
    const float* cW1    = (const float*)d_in[7];
    const float* cb1    = (const float*)d_in[8];
    const float* cW2    = (const float*)d_in[9];
    const float* cb2    = (const float*)d_in[10];
    const float* cW3    = (const float*)d_in[11];
    const float* cb3    = (const float*)d_in[12];
    float* out = (float*)d_out;

    const int n = in_sizes[0] / 3;

    reset_kernel<<<1, 1>>>();
    mask_zero_compact<<<(n + 255) / 256, 256>>>(x, out, n);
    ngp_fwd<<<(n + 127) / 128, 128>>>(x, d, tables, dW1, db1, dW2, db2,
                                      cW1, cb1, cW2, cb2, cW3, cb3, out, n);
}

// round 3
// speedup vs baseline: 1.6020x; 1.0237x over previous
#include <cuda_runtime.h>
#include <math.h>

typedef unsigned int u32;
typedef unsigned long long u64;

#define T_SIZE 524288u
#define T_MASK (T_SIZE - 1u)
#define HPI2 2654435761u
#define HPI3 805459861u
#define MAXN 1048576

__device__ int g_cnt;
__device__ int g_idx[MAXN];
__device__ float4 g_pt[2 * MAXN];  // slot*2+0 = (xc0,xc1,xc2,d0); slot*2+1 = (d1,d2,-,-)

__constant__ float c_NL[16] = {16.f, 22.f, 30.f, 42.f, 58.f, 80.f, 111.f, 153.f,
                               212.f, 293.f, 406.f, 561.f, 775.f, 1071.f, 1481.f, 2046.f};

// ---- weights in constant memory (reads go through LDC/LDCU const port, off L1TEX) ----
__constant__ ulonglong2 c_dW1v[512];   // 32x64  = 2048 f
__constant__ ulonglong2 c_db1v[16];    // 64 f
__constant__ ulonglong2 c_dW2v[256];   // 64x16  = 1024 f
__constant__ ulonglong2 c_db2v[4];     // 16 f
__constant__ ulonglong2 c_cW1v[688];   // 43x64  = 2752 f
__constant__ ulonglong2 c_cb1v[16];    // 64 f
__constant__ ulonglong2 c_cW2v[1024];  // 64x64  = 4096 f
__constant__ ulonglong2 c_cb2v[16];    // 64 f
__constant__ float      c_cW3[192];    // 64x3
__constant__ float      c_cb3[3];

// ---- f32x2 packed-FMA helpers (sm_103a FFMA2, PTX-only) ----
__device__ __forceinline__ u64 fma2(u64 a, u64 b, u64 c) {
    u64 d;
    asm("fma.rn.f32x2 %0, %1, %2, %3;" : "=l"(d) : "l"(a), "l"(b), "l"(c));
    return d;
}
__device__ __forceinline__ u64 dup2(float v) {
    u64 d;
    asm("mov.b64 %0, {%1, %1};" : "=l"(d) : "f"(v));
    return d;
}
__device__ __forceinline__ float2 unpack2(u64 v) {
    float2 r;
    asm("mov.b64 {%0, %1}, %2;" : "=f"(r.x), "=f"(r.y) : "l"(v));
    return r;
}

// accumulate v * row(64 floats) into 64-wide packed accumulator
__device__ __forceinline__ void crow64(u64 acc[32], float v, const ulonglong2* row) {
    const u64 dv = dup2(v);
    #pragma unroll
    for (int k = 0; k < 16; k++) {
        const ulonglong2 w = row[k];
        acc[2 * k + 0] = fma2(dv, w.x, acc[2 * k + 0]);
        acc[2 * k + 1] = fma2(dv, w.y, acc[2 * k + 1]);
    }
}

// ------------------------------------------------------------------
// Kernel 1: mask, zero dead outputs, compact indices + coords/dirs
// ------------------------------------------------------------------
__global__ __launch_bounds__(256)
void mask_zero_compact(const float* __restrict__ x, const float* __restrict__ dvec,
                       float* __restrict__ out, int n) {
    const int i = blockIdx.x * blockDim.x + threadIdx.x;
    const bool valid = (i < n);
    bool m = false;
    float xs0 = 0.f, xs1 = 0.f, xs2 = 0.f;
    if (valid) {
        xs0 = x[3 * i + 0] * (1.0f / 3.0f);
        xs1 = x[3 * i + 1] * (1.0f / 3.0f);
        xs2 = x[3 * i + 2] * (1.0f / 3.0f);
        m = (fabsf(xs0) < 0.5f) && (fabsf(xs1) < 0.5f) && (fabsf(xs2) < 0.5f);
    }
    const u32 bal = __ballot_sync(0xffffffffu, m);
    const int lane = threadIdx.x & 31;
    int base = 0;
    if (lane == 0 && bal) base = atomicAdd(&g_cnt, __popc(bal));
    base = __shfl_sync(0xffffffffu, base, 0);
    if (m) {
        const int slot = base + __popc(bal & ((1u << lane) - 1u));
        g_idx[slot] = i;
        // inside the box, clip is a no-op; store normalized coords directly
        const float d0 = dvec[3 * i + 0];
        const float d1 = dvec[3 * i + 1];
        const float d2 = dvec[3 * i + 2];
        g_pt[2 * slot + 0] = make_float4(xs0 + 0.5f, xs1 + 0.5f, xs2 + 0.5f, d0);
        g_pt[2 * slot + 1] = make_float4(d1, d2, 0.f, 0.f);
    } else if (valid) {
        out[3 * i + 0] = 0.0f;
        out[3 * i + 1] = 0.0f;
        out[3 * i + 2] = 0.0f;
        out[3 * n + i] = 0.0f;  // exp(-10000) underflows to 0
    }
}

// ------------------------------------------------------------------
// hash fetch for one level: 8 gathers + trilinear weights
// ------------------------------------------------------------------
__device__ __forceinline__ void hash_fetch(int lev, float xc0, float xc1, float xc2,
                                           const float2* __restrict__ tb2,
                                           float2 e[8], float& w0, float& w1, float& w2) {
    const float nl = c_NL[lev];
    const float xn0 = xc0 * nl, xn1 = xc1 * nl, xn2 = xc2 * nl;
    const float fl0 = floorf(xn0), fl1 = floorf(xn1), fl2 = floorf(xn2);
    w0 = xn0 - fl0; w1 = xn1 - fl1; w2 = xn2 - fl2;
    const u32 f0 = (u32)fl0, f1 = (u32)fl1, f2 = (u32)fl2;
    const u32 cx = (u32)ceilf(xn0), cy = (u32)ceilf(xn1), cz = (u32)ceilf(xn2);
    const u32 hyf = f1 * HPI2, hyc = cy * HPI2;
    const u32 hzf = f2 * HPI3, hzc = cz * HPI3;
    const float2* __restrict__ tl = tb2 + (size_t)lev * T_SIZE;
    #pragma unroll
    for (int v = 0; v < 8; v++) {
        const u32 h = (((v & 1) ? cx : f0)
                     ^ ((v & 2) ? hyc : hyf)
                     ^ ((v & 4) ? hzc : hzf)) & T_MASK;
        e[v] = __ldg(tl + h);
    }
}

__device__ __forceinline__ void accum_level(int lev, const float2 e[8],
                                            float w0, float w1, float w2, u64 h1x2[32]) {
    const float v0 = 1.0f - w0, v1 = 1.0f - w1, v2 = 1.0f - w2;
    float fa = 0.0f, fb = 0.0f;
    #pragma unroll
    for (int v = 0; v < 8; v++) {
        const float wc = ((v & 1) ? w0 : v0) * ((v & 2) ? w1 : v1) * ((v & 4) ? w2 : v2);
        fa = fmaf(wc, e[v].x, fa);
        fb = fmaf(wc, e[v].y, fb);
    }
    const u64 dA = dup2(fa), dB = dup2(fb);
    const ulonglong2* Wa = c_dW1v + lev * 32;       // row 2*lev
    const ulonglong2* Wb = c_dW1v + lev * 32 + 16;  // row 2*lev+1
    #pragma unroll
    for (int k = 0; k < 16; k++) {
        const ulonglong2 a = Wa[k];
        const ulonglong2 b = Wb[k];
        h1x2[2 * k + 0] = fma2(dA, a.x, fma2(dB, b.x, h1x2[2 * k + 0]));
        h1x2[2 * k + 1] = fma2(dA, a.y, fma2(dB, b.y, h1x2[2 * k + 1]));
    }
}

// ------------------------------------------------------------------
// Kernel 2: fused NGP forward on compacted points
// ------------------------------------------------------------------
__global__ __launch_bounds__(128, 4)
void ngp_fwd(const float* __restrict__ tables, float* __restrict__ out, int n)
{
    const int slot = blockIdx.x * 128 + threadIdx.x;
    if (slot >= g_cnt) return;
    const int idx = g_idx[slot];

    const float4 p0 = g_pt[2 * slot + 0];
    const float4 p1 = g_pt[2 * slot + 1];
    const float xc0 = p0.x, xc1 = p0.y, xc2 = p0.z;
    const float d0v = p0.w, d1v = p1.x, d2v = p1.y;

    const float2* __restrict__ tb2 = (const float2*)tables;

    // ---- density layer 1 (32 -> 64), level-pipelined gathers ----
    u64 h1x2[32];
    #pragma unroll
    for (int k = 0; k < 16; k++) {
        const ulonglong2 b = c_db1v[k];
        h1x2[2 * k + 0] = b.x;
        h1x2[2 * k + 1] = b.y;
    }

    float2 pe[8];
    float pw0, pw1, pw2;
    hash_fetch(0, xc0, xc1, xc2, tb2, pe, pw0, pw1, pw2);

    #pragma unroll 1
    for (int lev = 1; lev < 16; lev++) {
        float2 ne[8];
        float nw0, nw1, nw2;
        hash_fetch(lev, xc0, xc1, xc2, tb2, ne, nw0, nw1, nw2);  // loads in flight...
        accum_level(lev - 1, pe, pw0, pw1, pw2, h1x2);           // ...while computing
        #pragma unroll
        for (int v = 0; v < 8; v++) pe[v] = ne[v];
        pw0 = nw0; pw1 = nw1; pw2 = nw2;
    }
    accum_level(15, pe, pw0, pw1, pw2, h1x2);

    // ---- density layer 2 (64 -> 16), relu on inputs ----
    u64 h16x2[8];
    #pragma unroll
    for (int j = 0; j < 4; j++) {
        const ulonglong2 b = c_db2v[j];
        h16x2[2 * j + 0] = b.x;
        h16x2[2 * j + 1] = b.y;
    }
    #pragma unroll
    for (int k = 0; k < 32; k++) {
        const float2 p = unpack2(h1x2[k]);
        const u64 d0 = dup2(fmaxf(p.x, 0.0f));
        const u64 d1 = dup2(fmaxf(p.y, 0.0f));
        const ulonglong2* r0 = c_dW2v + (2 * k) * 4;  // row = 16 floats = 4 u2
        const ulonglong2* r1 = r0 + 4;
        #pragma unroll
        for (int j = 0; j < 4; j++) {
            const ulonglong2 A = r0[j];
            const ulonglong2 B = r1[j];
            h16x2[2 * j + 0] = fma2(d0, A.x, fma2(d1, B.x, h16x2[2 * j + 0]));
            h16x2[2 * j + 1] = fma2(d0, A.y, fma2(d1, B.y, h16x2[2 * j + 1]));
        }
    }

    float h16[16];
    #pragma unroll
    for (int j = 0; j < 8; j++) {
        const float2 p = unpack2(h16x2[j]);
        h16[2 * j + 0] = p.x;
        h16[2 * j + 1] = p.y;
    }
    const float sigma = expf(h16[0]);

    // ---- color layer 1 (43 -> 64), inputs streamed (no cin array) ----
    u64 g1x2[32];
    #pragma unroll
    for (int k = 0; k < 16; k++) {
        const ulonglong2 b = c_cb1v[k];
        g1x2[2 * k + 0] = b.x;
        g1x2[2 * k + 1] = b.y;
    }
    #pragma unroll
    for (int i = 0; i < 16; i++) crow64(g1x2, h16[i], c_cW1v + i * 16);
    crow64(g1x2, d0v, c_cW1v + 16 * 16);
    crow64(g1x2, d1v, c_cW1v + 17 * 16);
    crow64(g1x2, d2v, c_cW1v + 18 * 16);
    {
        float f = 1.0f;
        #pragma unroll
        for (int i = 0; i < 4; i++) {
            float s0, c0, s1, c1, s2, c2;
            sincosf(f * d0v, &s0, &c0);
            sincosf(f * d1v, &s1, &c1);
            sincosf(f * d2v, &s2, &c2);
            const int r = 19 + 6 * i;
            crow64(g1x2, s0, c_cW1v + (r + 0) * 16);
            crow64(g1x2, s1, c_cW1v + (r + 1) * 16);
            crow64(g1x2, s2, c_cW1v + (r + 2) * 16);
            crow64(g1x2, c0, c_cW1v + (r + 3) * 16);
            crow64(g1x2, c1, c_cW1v + (r + 4) * 16);
            crow64(g1x2, c2, c_cW1v + (r + 5) * 16);
            f *= 2.0f;
        }
    }

    // ---- color layer 2 (64 -> 64) + layer 3 (64 -> 3), two 32-output passes ----
    float o0 = c_cb3[0], o1 = c_cb3[1], o2 = c_cb3[2];
    #pragma unroll
    for (int half = 0; half < 2; half++) {
        u64 g2h[16];  // 32 outputs
        #pragma unroll
        for (int j = 0; j < 8; j++) {
            const ulonglong2 b = c_cb2v[half * 8 + j];
            g2h[2 * j + 0] = b.x;
            g2h[2 * j + 1] = b.y;
        }
        #pragma unroll
        for (int k = 0; k < 32; k++) {
            const float2 p = unpack2(g1x2[k]);
            const u64 d0 = dup2(fmaxf(p.x, 0.0f));
            const u64 d1 = dup2(fmaxf(p.y, 0.0f));
            const ulonglong2* r0 = c_cW2v + (2 * k) * 16 + half * 8;  // row = 64 f = 16 u2
            const ulonglong2* r1 = r0 + 16;
            #pragma unroll
            for (int j = 0; j < 8; j++) {
                const ulonglong2 A = r0[j];
                const ulonglong2 B = r1[j];
                g2h[2 * j + 0] = fma2(d0, A.x, fma2(d1, B.x, g2h[2 * j + 0]));
                g2h[2 * j + 1] = fma2(d0, A.y, fma2(d1, B.y, g2h[2 * j + 1]));
            }
        }
        #pragma unroll
        for (int j = 0; j < 16; j++) {
            const float2 p = unpack2(g2h[j]);
            const float a0 = fmaxf(p.x, 0.0f);
            const float a1 = fmaxf(p.y, 0.0f);
            const int i0 = half * 32 + 2 * j;
            o0 = fmaf(a0, c_cW3[i0 * 3 + 0], o0);
            o1 = fmaf(a0, c_cW3[i0 * 3 + 1], o1);
            o2 = fmaf(a0, c_cW3[i0 * 3 + 2], o2);
            o0 = fmaf(a1, c_cW3[i0 * 3 + 3], o0);
            o1 = fmaf(a1, c_cW3[i0 * 3 + 4], o1);
            o2 = fmaf(a1, c_cW3[i0 * 3 + 5], o2);
        }
    }

    out[3 * idx + 0] = 1.0f / (1.0f + expf(-o0));
    out[3 * idx + 1] = 1.0f / (1.0f + expf(-o1));
    out[3 * idx + 2] = 1.0f / (1.0f + expf(-o2));
    out[3 * n + idx] = sigma;
}

extern "C" void kernel_launch(void* const* d_in, const int* in_sizes, int n_in,
                              void* d_out, int out_size) {
    const float* x      = (const float*)d_in[0];
    const float* d      = (const float*)d_in[1];
    const float* tables = (const float*)d_in[2];
    float* out = (float*)d_out;
    const int n = in_sizes[0] / 3;

    // weights -> constant memory (D2D async copies; graph-capturable memcpy nodes)
    cudaMemcpyToSymbolAsync(c_dW1v, d_in[3],  2048 * 4, 0, cudaMemcpyDeviceToDevice, 0);
    cudaMemcpyToSymbolAsync(c_db1v, d_in[4],    64 * 4, 0, cudaMemcpyDeviceToDevice, 0);
    cudaMemcpyToSymbolAsync(c_dW2v, d_in[5],  1024 * 4, 0, cudaMemcpyDeviceToDevice, 0);
    cudaMemcpyToSymbolAsync(c_db2v, d_in[6],    16 * 4, 0, cudaMemcpyDeviceToDevice, 0);
    cudaMemcpyToSymbolAsync(c_cW1v, d_in[7],  2752 * 4, 0, cudaMemcpyDeviceToDevice, 0);
    cudaMemcpyToSymbolAsync(c_cb1v, d_in[8],    64 * 4, 0, cudaMemcpyDeviceToDevice, 0);
    cudaMemcpyToSymbolAsync(c_cW2v, d_in[9],  4096 * 4, 0, cudaMemcpyDeviceToDevice, 0);
    cudaMemcpyToSymbolAsync(c_cb2v, d_in[10],   64 * 4, 0, cudaMemcpyDeviceToDevice, 0);
    cudaMemcpyToSymbolAsync(c_cW3,  d_in[11],  192 * 4, 0, cudaMemcpyDeviceToDevice, 0);
    cudaMemcpyToSymbolAsync(c_cb3,  d_in[12],    3 * 4, 0, cudaMemcpyDeviceToDevice, 0);

    // reset compaction counter (memset node)
    void* cnt_addr = nullptr;
    cudaGetSymbolAddress(&cnt_addr, g_cnt);
    cudaMemsetAsync(cnt_addr, 0, sizeof(int), 0);

    mask_zero_compact<<<(n + 255) / 256, 256>>>(x, d, out, n);
    ngp_fwd<<<(n + 127) / 128, 128>>>(tables, out, n);
}